// round 1
// baseline (speedup 1.0000x reference)
#include <cuda_runtime.h>
#include <math.h>
#include <stdint.h>

// Problem constants
#define Bsz   4
#define Lseq  256
#define Dm    768
#define Hh    384
#define G4    1536      // 4*H
#define NPAIR 8         // 4 windows x 2 directions
#define Mtot  1024      // B*L

// Scratch (device globals; no dynamic allocation allowed)
__device__ float g_x[Mtot * Dm];                 // scattered input  (3 MB)
__device__ float g_P[(size_t)NPAIR * Mtot * G4]; // input projections (50 MB)
__device__ float g_H[2][(size_t)NPAIR * Mtot * Hh]; // ping-pong hidden (25 MB)
__device__ float g_C[(size_t)NPAIR * Mtot * Hh];    // cell state (12.6 MB)

// ---------------------------------------------------------------------------
// Kernel 1: valid-scatter.  One block per batch row.
// dest[l] = cumsum(valid)-1 if valid else drop; x[b,dest,:] = seq[b,l,:], rest 0
// ---------------------------------------------------------------------------
__global__ void k_scatter(const float* __restrict__ seq, const int* __restrict__ valid)
{
    int b = blockIdx.x;
    __shared__ int scan[Lseq];
    __shared__ int dest[Lseq];
    int tid = threadIdx.x;                 // 256 threads, one per l
    int v = valid[b * Lseq + tid];
    scan[tid] = v;
    __syncthreads();
    // inclusive Hillis-Steele scan
    for (int off = 1; off < Lseq; off <<= 1) {
        int val = (tid >= off) ? scan[tid - off] : 0;
        __syncthreads();
        scan[tid] += val;
        __syncthreads();
    }
    dest[tid] = (v == 1) ? (scan[tid] - 1) : -1;
    __syncthreads();

    float* xb = g_x + (size_t)b * Lseq * Dm;
    for (int i = tid; i < Lseq * Dm; i += 256) xb[i] = 0.f;
    __syncthreads();
    const float* sb = seq + (size_t)b * Lseq * Dm;
    for (int i = tid; i < Lseq * Dm; i += 256) {
        int l = i / Dm;
        int d = i - l * Dm;
        int dl = dest[l];
        if (dl >= 0) xb[dl * Dm + d] = sb[i];
    }
}

// ---------------------------------------------------------------------------
// Kernel 2: zero H[0] and C (every launch -> deterministic under graph replay)
// ---------------------------------------------------------------------------
__global__ void k_zero()
{
    size_t n = (size_t)NPAIR * Mtot * Hh;
    for (size_t i = (size_t)blockIdx.x * 256 + threadIdx.x; i < n; i += (size_t)gridDim.x * 256) {
        g_H[0][i] = 0.f;
        g_C[i] = 0.f;
    }
}

// ---------------------------------------------------------------------------
// Kernel 3: input projection GEMM.
// P[pair][t][n] = sum_k x[t][k] * W_ih[pair][n][k] + (b_ih+b_hh)[pair][n]
// Classic 128x128x8 SGEMM, 8x8 per thread, 256 threads. blockIdx.z = pair.
// ---------------------------------------------------------------------------
__global__ __launch_bounds__(256, 2) void k_proj(
    const float* __restrict__ wf, const float* __restrict__ wb,
    const float* __restrict__ bif, const float* __restrict__ bhf,
    const float* __restrict__ bib, const float* __restrict__ bhb)
{
    int pair = blockIdx.z, nw = pair >> 1, dir = pair & 1;
    const float* W  = (dir ? wb : wf) + (size_t)nw * G4 * Dm;
    const float* b1 = (dir ? bib : bif) + (size_t)nw * G4;
    const float* b2 = (dir ? bhb : bhf) + (size_t)nw * G4;
    float* Cout = g_P + (size_t)pair * Mtot * G4;
    const float* A = g_x;

    __shared__ float As[8][128];
    __shared__ float Bs[8][128];
    int tid = threadIdx.x;
    int m0 = blockIdx.y * 128, n0 = blockIdx.x * 128;
    int lr = tid >> 1, lk = (tid & 1) * 4;
    int tx = tid & 15, ty = tid >> 4;

    float acc[8][8];
#pragma unroll
    for (int i = 0; i < 8; i++)
#pragma unroll
        for (int j = 0; j < 8; j++) acc[i][j] = 0.f;

    const float* Aptr = A + (size_t)(m0 + lr) * Dm + lk;
    const float* Bptr = W + (size_t)(n0 + lr) * Dm + lk;

    for (int kt = 0; kt < Dm; kt += 8) {
        float4 av = *(const float4*)(Aptr + kt);
        float4 bv = *(const float4*)(Bptr + kt);
        __syncthreads();
        As[lk + 0][lr] = av.x; As[lk + 1][lr] = av.y; As[lk + 2][lr] = av.z; As[lk + 3][lr] = av.w;
        Bs[lk + 0][lr] = bv.x; Bs[lk + 1][lr] = bv.y; Bs[lk + 2][lr] = bv.z; Bs[lk + 3][lr] = bv.w;
        __syncthreads();
#pragma unroll
        for (int k = 0; k < 8; k++) {
            float a[8], bb[8];
            *(float4*)&a[0]  = *(const float4*)&As[k][ty * 4];
            *(float4*)&a[4]  = *(const float4*)&As[k][64 + ty * 4];
            *(float4*)&bb[0] = *(const float4*)&Bs[k][tx * 4];
            *(float4*)&bb[4] = *(const float4*)&Bs[k][64 + tx * 4];
#pragma unroll
            for (int i = 0; i < 8; i++)
#pragma unroll
                for (int j = 0; j < 8; j++) acc[i][j] += a[i] * bb[j];
        }
    }
#pragma unroll
    for (int i = 0; i < 8; i++) {
        int r = m0 + ((i < 4) ? (ty * 4 + i) : (64 + ty * 4 + (i - 4)));
#pragma unroll
        for (int j = 0; j < 8; j++) {
            int c = n0 + ((j < 4) ? (tx * 4 + j) : (64 + tx * 4 + (j - 4)));
            Cout[(size_t)r * G4 + c] = acc[i][j] + b1[c] + b2[c];
        }
    }
}

// ---------------------------------------------------------------------------
// Kernel 4: one LSTM step for all (b,l) chains and all active (window,dir)
// pairs.  gates = P[token] + H_cur @ W_hh^T, then elementwise LSTM update.
// H ping-pongs between g_H[s&1] (read) and g_H[(s+1)&1] (write) -> no races.
// Gate columns interleaved in smem as n = hcol*4 + gate so each thread holds
// all 4 gates of its h-columns for the fused epilogue.
// ---------------------------------------------------------------------------
__global__ __launch_bounds__(256, 2) void k_step(
    const float* __restrict__ whf, const float* __restrict__ whb, int s)
{
    int pair = blockIdx.z, nw = pair >> 1, dir = pair & 1;
    int w = 3 + 2 * nw;                 // windows 3,5,7,9
    if (s >= w) return;                 // pair finished
    int half = nw + 1;
    int j = dir ? (w - 1 - s) : s;

    const float* W = (dir ? whb : whf) + (size_t)nw * G4 * Hh;
    const float* Hcur = g_H[s & 1] + (size_t)pair * Mtot * Hh;
    float* Hnext = g_H[(s + 1) & 1] + (size_t)pair * Mtot * Hh;
    float* Cst = g_C + (size_t)pair * Mtot * Hh;
    const float* Pp = g_P + (size_t)pair * Mtot * G4;

    __shared__ float As[8][128];
    __shared__ float Bs[8][128];
    int tid = threadIdx.x;
    int m0 = blockIdx.y * 128;          // 8 m-tiles of 128 positions
    int n0h = blockIdx.x * 32;          // 12 h-tiles of 32 cols (x4 gates = 128)
    int lr = tid >> 1, lk = (tid & 1) * 4;
    int bgate = lr & 3, bh = lr >> 2;   // B col n=lr -> (hcol=n>>2, gate=n&3)
    int tx = tid & 15, ty = tid >> 4;

    float acc[8][8];
#pragma unroll
    for (int i = 0; i < 8; i++)
#pragma unroll
        for (int jj = 0; jj < 8; jj++) acc[i][jj] = 0.f;

    const float* Aptr = Hcur + (size_t)(m0 + lr) * Hh + lk;
    const float* Bptr = W + (size_t)(bgate * Hh + n0h + bh) * Hh + lk;

    for (int kt = 0; kt < Hh; kt += 8) {
        float4 av = *(const float4*)(Aptr + kt);
        float4 bv = *(const float4*)(Bptr + kt);
        __syncthreads();
        As[lk + 0][lr] = av.x; As[lk + 1][lr] = av.y; As[lk + 2][lr] = av.z; As[lk + 3][lr] = av.w;
        Bs[lk + 0][lr] = bv.x; Bs[lk + 1][lr] = bv.y; Bs[lk + 2][lr] = bv.z; Bs[lk + 3][lr] = bv.w;
        __syncthreads();
#pragma unroll
        for (int k = 0; k < 8; k++) {
            float a[8], bb[8];
            *(float4*)&a[0]  = *(const float4*)&As[k][ty * 4];
            *(float4*)&a[4]  = *(const float4*)&As[k][64 + ty * 4];
            *(float4*)&bb[0] = *(const float4*)&Bs[k][tx * 4];
            *(float4*)&bb[4] = *(const float4*)&Bs[k][64 + tx * 4];
#pragma unroll
            for (int i = 0; i < 8; i++)
#pragma unroll
                for (int jj = 0; jj < 8; jj++) acc[i][jj] += a[i] * bb[jj];
        }
    }

    // Fused LSTM epilogue.  acc[i][j<4]: hcol=tx, gate=j ; acc[i][j>=4]: hcol=16+tx, gate=j-4
#pragma unroll
    for (int i = 0; i < 8; i++) {
        int r = (i < 4) ? (ty * 4 + i) : (64 + ty * 4 + (i - 4));
        int p = m0 + r;
        int l = p & 255;
        int t = l - half + j;
        bool mask = (t >= 0) && (t < Lseq);
        int tcl = min(max(t, 0), Lseq - 1);
        const float* Pr = Pp + (size_t)((p & ~255) | tcl) * G4;
#pragma unroll
        for (int cb = 0; cb < 2; cb++) {
            int hc = n0h + cb * 16 + tx;
            int jb = cb * 4;
            float gi = acc[i][jb + 0] + Pr[hc];
            float gf = acc[i][jb + 1] + Pr[Hh + hc];
            float gg = acc[i][jb + 2] + Pr[2 * Hh + hc];
            float go = acc[i][jb + 3] + Pr[3 * Hh + hc];
            float si = 1.f / (1.f + __expf(-gi));
            float sf = 1.f / (1.f + __expf(-gf));
            float tg = tanhf(gg);
            float so = 1.f / (1.f + __expf(-go));
            size_t idx = (size_t)p * Hh + hc;
            float c_old = Cst[idx];
            float c_new = sf * c_old + si * tg;
            float h_new = so * tanhf(c_new);
            if (mask) {
                Cst[idx] = c_new;
                Hnext[idx] = h_new;
            } else {
                Hnext[idx] = Hcur[idx];   // carry state through masked step
            }
        }
    }
}

// ---------------------------------------------------------------------------
// Kernel 5: attention over 4 windows + residual + linear head (D=768 -> 9).
// One block per position p.  All odd windows -> final H lives in g_H[1].
// ---------------------------------------------------------------------------
__device__ __forceinline__ float blockReduce(float v)
{
    __shared__ float sred[8];
#pragma unroll
    for (int o = 16; o > 0; o >>= 1) v += __shfl_xor_sync(0xffffffffu, v, o);
    int wid = threadIdx.x >> 5, ln = threadIdx.x & 31;
    __syncthreads();
    if (ln == 0) sred[wid] = v;
    __syncthreads();
    float r = 0.f;
    if (wid == 0) {
        r = (ln < 8) ? sred[ln] : 0.f;
#pragma unroll
        for (int o = 4; o > 0; o >>= 1) r += __shfl_xor_sync(0xffffffffu, r, o);
    }
    return r;   // valid on thread 0
}

__global__ __launch_bounds__(256) void k_final(const float* __restrict__ lw,
                                               const float* __restrict__ lb,
                                               float* __restrict__ out)
{
    int p = blockIdx.x;
    int tid = threadIdx.x;
    const float* xp = g_x + (size_t)p * Dm;
    float xv[3], mv[4][3];
    __shared__ float attn_s[4];
#pragma unroll
    for (int q = 0; q < 3; q++) xv[q] = xp[tid + q * 256];

    float logits[4];
#pragma unroll
    for (int nw = 0; nw < 4; nw++) {
        const float* hf = g_H[1] + ((size_t)(nw * 2) * Mtot + p) * Hh;
        const float* hb = g_H[1] + ((size_t)(nw * 2 + 1) * Mtot + p) * Hh;
#pragma unroll
        for (int q = 0; q < 3; q++) {
            int d = tid + q * 256;
            mv[nw][q] = (d < Hh) ? hf[d] : hb[d - Hh];
        }
        float part = xv[0] * mv[nw][0] + xv[1] * mv[nw][1] + xv[2] * mv[nw][2];
        logits[nw] = blockReduce(part);
    }
    if (tid == 0) {
        float sc = rsqrtf(768.f);
        float l0 = logits[0] * sc, l1 = logits[1] * sc, l2 = logits[2] * sc, l3 = logits[3] * sc;
        float mx = fmaxf(fmaxf(l0, l1), fmaxf(l2, l3));
        float e0 = __expf(l0 - mx), e1 = __expf(l1 - mx), e2 = __expf(l2 - mx), e3 = __expf(l3 - mx);
        float inv = 1.f / (e0 + e1 + e2 + e3);
        attn_s[0] = e0 * inv; attn_s[1] = e1 * inv; attn_s[2] = e2 * inv; attn_s[3] = e3 * inv;
    }
    __syncthreads();
    float a0 = attn_s[0], a1 = attn_s[1], a2 = attn_s[2], a3 = attn_s[3];
    float ov[3];
#pragma unroll
    for (int q = 0; q < 3; q++)
        ov[q] = xv[q] + a0 * mv[0][q] + a1 * mv[1][q] + a2 * mv[2][q] + a3 * mv[3][q];

    for (int k = 0; k < 9; k++) {
        float part = 0.f;
#pragma unroll
        for (int q = 0; q < 3; q++) part += ov[q] * lw[(size_t)k * Dm + tid + q * 256];
        float tot = blockReduce(part);
        if (tid == 0) out[p * 9 + k] = tot + lb[k];
    }
}

// ---------------------------------------------------------------------------
extern "C" void kernel_launch(void* const* d_in, const int* in_sizes, int n_in,
                              void* d_out, int out_size)
{
    const float* seq   = (const float*)d_in[0];
    const int*   valid = (const int*)d_in[1];
    const float* wif   = (const float*)d_in[2];
    const float* whf   = (const float*)d_in[3];
    const float* bif   = (const float*)d_in[4];
    const float* bhf   = (const float*)d_in[5];
    const float* wib   = (const float*)d_in[6];
    const float* whb   = (const float*)d_in[7];
    const float* bib   = (const float*)d_in[8];
    const float* bhb   = (const float*)d_in[9];
    const float* lw    = (const float*)d_in[10];
    const float* lb    = (const float*)d_in[11];
    float* out = (float*)d_out;

    k_scatter<<<Bsz, 256>>>(seq, valid);
    k_zero<<<512, 256>>>();
    k_proj<<<dim3(12, 8, 8), 256>>>(wif, wib, bif, bhf, bib, bhb);
    for (int s = 0; s < 9; s++)
        k_step<<<dim3(12, 8, 8), 256>>>(whf, whb, s);
    k_final<<<Mtot, 256>>>(lw, lb, out);
}

// round 3
// speedup vs baseline: 1.8340x; 1.8340x over previous
#include <cuda_runtime.h>
#include <cuda_bf16.h>
#include <math.h>
#include <stdint.h>

// ---------------- problem constants ----------------
#define Bsz   4
#define Lseq  256
#define Dm    768
#define Hh    384
#define G4    1536
#define NPAIR 8
#define Mtot  1024
#define NT    12            // n-tiles of 128 over 1536
#define WR    36            // smem words per 64-elem bf16 row (64*2B + 8B pad)/4
#define SMW   18432         // total smem words: 4 buffers * 128 * 36
#define SMEM_BYTES (SMW * 4)

// ---------------- device scratch ----------------
__device__ __align__(16) float          g_x[Mtot * Dm];
__device__ __align__(16) __nv_bfloat16  g_Xhi[Mtot * Dm];
__device__ __align__(16) __nv_bfloat16  g_Xlo[Mtot * Dm];
__device__ __align__(16) __nv_bfloat16  g_WhhHi[(size_t)NPAIR * G4 * Hh];
__device__ __align__(16) __nv_bfloat16  g_WhhLo[(size_t)NPAIR * G4 * Hh];
__device__ __align__(16) __nv_bfloat16  g_WihHi[(size_t)NPAIR * G4 * Dm];
__device__ __align__(16) __nv_bfloat16  g_WihLo[(size_t)NPAIR * G4 * Dm];
__device__ __align__(16) float          g_bias[NPAIR * G4];            // interleaved
__device__ __align__(16) float          g_P[(size_t)NPAIR * Mtot * G4]; // interleaved n
__device__ __align__(16) __nv_bfloat16  g_Hhi[2][(size_t)NPAIR * Mtot * Hh];
__device__ __align__(16) __nv_bfloat16  g_Hlo[2][(size_t)NPAIR * Mtot * Hh];
__device__ __align__(16) float          g_C[(size_t)NPAIR * Mtot * Hh];

// ---------------- mma.sync helper ----------------
#define MMA4(acc, a, b) \
    asm volatile("mma.sync.aligned.m16n8k16.row.col.f32.bf16.bf16.f32 " \
        "{%0,%1,%2,%3},{%4,%5,%6,%7},{%8,%9},{%0,%1,%2,%3};" \
        : "+f"((acc)[0]), "+f"((acc)[1]), "+f"((acc)[2]), "+f"((acc)[3]) \
        : "r"((a)[0]), "r"((a)[1]), "r"((a)[2]), "r"((a)[3]), \
          "r"((b)[0]), "r"((b)[1]))

// ---------------- kernel 1: valid-scatter ----------------
__global__ void k_scatter(const float* __restrict__ seq, const int* __restrict__ valid)
{
    int b = blockIdx.x;
    __shared__ int scan[Lseq];
    __shared__ int dest[Lseq];
    int tid = threadIdx.x;
    int v = valid[b * Lseq + tid];
    scan[tid] = v;
    __syncthreads();
    for (int off = 1; off < Lseq; off <<= 1) {
        int val = (tid >= off) ? scan[tid - off] : 0;
        __syncthreads();
        scan[tid] += val;
        __syncthreads();
    }
    dest[tid] = (v == 1) ? (scan[tid] - 1) : -1;
    __syncthreads();
    float* xb = g_x + (size_t)b * Lseq * Dm;
    for (int i = tid; i < Lseq * Dm; i += 256) xb[i] = 0.f;
    __syncthreads();
    const float* sb = seq + (size_t)b * Lseq * Dm;
    for (int i = tid; i < Lseq * Dm; i += 256) {
        int l = i / Dm, d = i - l * Dm;
        int dl = dest[l];
        if (dl >= 0) xb[dl * Dm + d] = sb[i];
    }
}

// ---------------- kernel 2: split x into bf16 hi/lo ----------------
__global__ void k_convX()
{
    int n = Mtot * Dm;
    for (int i = blockIdx.x * 256 + threadIdx.x; i < n; i += gridDim.x * 256) {
        float v = g_x[i];
        __nv_bfloat16 hi = __float2bfloat16(v);
        g_Xhi[i] = hi;
        g_Xlo[i] = __float2bfloat16(v - __bfloat162float(hi));
    }
}

// ---------------- kernel 3: zero H[0], C ----------------
__global__ void k_zero()
{
    size_t n = (size_t)NPAIR * Mtot * Hh;
    for (size_t i = (size_t)blockIdx.x * 256 + threadIdx.x; i < n; i += (size_t)gridDim.x * 256) {
        g_Hhi[0][i] = __float2bfloat16(0.f);
        g_Hlo[0][i] = __float2bfloat16(0.f);
        g_C[i] = 0.f;
    }
}

// ---------------- kernel 4: weight conversion (interleaved rows, hi/lo split) ----
// n_il = ntile*128 + hc_local*4 + gate  maps to original n = gate*Hh + ntile*32 + hc_local
__device__ __forceinline__ int n_orig(int n_il)
{
    int ntile = n_il >> 7, nl = n_il & 127;
    return (nl & 3) * Hh + ntile * 32 + (nl >> 2);
}
__global__ void k_convW(const float* __restrict__ whf, const float* __restrict__ whb,
                        const float* __restrict__ wif, const float* __restrict__ wib,
                        const float* __restrict__ bif, const float* __restrict__ bhf,
                        const float* __restrict__ bib, const float* __restrict__ bhb)
{
    // W_hh  [pair][n_il][384]
    {
        size_t tot = (size_t)NPAIR * G4 * Hh;
        for (size_t i = (size_t)blockIdx.x * 256 + threadIdx.x; i < tot; i += (size_t)gridDim.x * 256) {
            int k = (int)(i % Hh);
            size_t r = i / Hh;
            int n_il = (int)(r % G4);
            int pair = (int)(r / G4);
            int nw = pair >> 1, dir = pair & 1;
            const float* W = (dir ? whb : whf) + (size_t)nw * G4 * Hh;
            float v = W[(size_t)n_orig(n_il) * Hh + k];
            __nv_bfloat16 hi = __float2bfloat16(v);
            g_WhhHi[i] = hi;
            g_WhhLo[i] = __float2bfloat16(v - __bfloat162float(hi));
        }
    }
    // W_ih  [pair][n_il][768]
    {
        size_t tot = (size_t)NPAIR * G4 * Dm;
        for (size_t i = (size_t)blockIdx.x * 256 + threadIdx.x; i < tot; i += (size_t)gridDim.x * 256) {
            int k = (int)(i % Dm);
            size_t r = i / Dm;
            int n_il = (int)(r % G4);
            int pair = (int)(r / G4);
            int nw = pair >> 1, dir = pair & 1;
            const float* W = (dir ? wib : wif) + (size_t)nw * G4 * Dm;
            float v = W[(size_t)n_orig(n_il) * Dm + k];
            __nv_bfloat16 hi = __float2bfloat16(v);
            g_WihHi[i] = hi;
            g_WihLo[i] = __float2bfloat16(v - __bfloat162float(hi));
        }
    }
    // bias (interleaved)
    {
        int tot = NPAIR * G4;
        for (int i = blockIdx.x * 256 + threadIdx.x; i < tot; i += gridDim.x * 256) {
            int n_il = i % G4, pair = i / G4;
            int nw = pair >> 1, dir = pair & 1;
            int n = n_orig(n_il);
            g_bias[i] = dir ? (bib[nw * G4 + n] + bhb[nw * G4 + n])
                            : (bif[nw * G4 + n] + bhf[nw * G4 + n]);
        }
    }
}

// ---------------- GEMM core: 128x128 tile, split-bf16, K chunked by 64 -------
// acc[mf][nf][4] fp32.  8 warps: wm = wid>>2 (2), wn = wid&3 (4).
__device__ __forceinline__ void gemm_core(
    float acc[4][4][4],
    const __nv_bfloat16* __restrict__ Ah, const __nv_bfloat16* __restrict__ Al, int strideA,
    const __nv_bfloat16* __restrict__ Bh, const __nv_bfloat16* __restrict__ Bl, int strideB,
    int nChunks, uint32_t* sm)
{
    int tid = threadIdx.x;
    int lane = tid & 31, wid = tid >> 5;
    int g = lane >> 2, t = lane & 3;
    int wm = wid >> 2, wn = wid & 3;
    uint32_t* As_h = sm;
    uint32_t* As_l = sm + 4608;
    uint32_t* Bs_h = sm + 9216;
    uint32_t* Bs_l = sm + 13824;

    int lrow = tid >> 3, lcol = tid & 7;    // for loads: 256 thr -> 32 rows x 8 u4

#pragma unroll 1
    for (int c = 0; c < nChunks; c++) {
        int kc = c * 64;
#pragma unroll
        for (int i = 0; i < 4; i++) {
            int row = lrow + i * 32;
            const uint4* pAh = (const uint4*)(Ah + (size_t)row * strideA + kc) + lcol;
            const uint4* pAl = (const uint4*)(Al + (size_t)row * strideA + kc) + lcol;
            const uint4* pBh = (const uint4*)(Bh + (size_t)row * strideB + kc) + lcol;
            const uint4* pBl = (const uint4*)(Bl + (size_t)row * strideB + kc) + lcol;
            ((uint4*)(As_h + row * WR))[lcol] = *pAh;
            ((uint4*)(As_l + row * WR))[lcol] = *pAl;
            ((uint4*)(Bs_h + row * WR))[lcol] = *pBh;
            ((uint4*)(Bs_l + row * WR))[lcol] = *pBl;
        }
        __syncthreads();

#pragma unroll
        for (int ks = 0; ks < 4; ks++) {
            int ko = ks * 8 + t;
            uint32_t b0[4][2], b1[4][2];
#pragma unroll
            for (int nf = 0; nf < 4; nf++) {
                int rn = (wn * 32 + nf * 8 + g) * WR + ko;
                b0[nf][0] = Bs_h[rn];
                b0[nf][1] = Bs_h[rn + 4];
                b1[nf][0] = Bs_l[rn];
                b1[nf][1] = Bs_l[rn + 4];
            }
            uint32_t a[4][4];
#pragma unroll
            for (int mf = 0; mf < 4; mf++) {
                int rm = (wm * 64 + mf * 16 + g) * WR + ko;
                a[mf][0] = As_h[rm];
                a[mf][1] = As_h[rm + 8 * WR];
                a[mf][2] = As_h[rm + 4];
                a[mf][3] = As_h[rm + 8 * WR + 4];
            }
#pragma unroll
            for (int mf = 0; mf < 4; mf++)
#pragma unroll
                for (int nf = 0; nf < 4; nf++) {
                    MMA4(acc[mf][nf], a[mf], b0[nf]);
                    MMA4(acc[mf][nf], a[mf], b1[nf]);
                }
#pragma unroll
            for (int mf = 0; mf < 4; mf++) {
                int rm = (wm * 64 + mf * 16 + g) * WR + ko;
                a[mf][0] = As_l[rm];
                a[mf][1] = As_l[rm + 8 * WR];
                a[mf][2] = As_l[rm + 4];
                a[mf][3] = As_l[rm + 8 * WR + 4];
            }
#pragma unroll
            for (int mf = 0; mf < 4; mf++)
#pragma unroll
                for (int nf = 0; nf < 4; nf++)
                    MMA4(acc[mf][nf], a[mf], b0[nf]);
        }
        __syncthreads();
    }
}

// store acc tile into Cs[128][132] (fp32)
__device__ __forceinline__ void stage_C(float acc[4][4][4], float* Cs)
{
    int tid = threadIdx.x;
    int lane = tid & 31, wid = tid >> 5;
    int g = lane >> 2, t = lane & 3;
    int wm = wid >> 2, wn = wid & 3;
#pragma unroll
    for (int mf = 0; mf < 4; mf++)
#pragma unroll
        for (int nf = 0; nf < 4; nf++) {
            int rm = wm * 64 + mf * 16 + g;
            int cn = wn * 32 + nf * 8 + t * 2;
            Cs[rm * 132 + cn]             = acc[mf][nf][0];
            Cs[rm * 132 + cn + 1]         = acc[mf][nf][1];
            Cs[(rm + 8) * 132 + cn]       = acc[mf][nf][2];
            Cs[(rm + 8) * 132 + cn + 1]   = acc[mf][nf][3];
        }
}

// ---------------- kernel 5: input projection ----------------
__global__ __launch_bounds__(256, 2) void k_proj_t()
{
    int ntile = blockIdx.x, mtile = blockIdx.y, pair = blockIdx.z;
    extern __shared__ uint32_t smw[];
    float acc[4][4][4];
#pragma unroll
    for (int i = 0; i < 4; i++)
#pragma unroll
        for (int j = 0; j < 4; j++)
#pragma unroll
            for (int q = 0; q < 4; q++) acc[i][j][q] = 0.f;

    const __nv_bfloat16* Ah = g_Xhi + (size_t)(mtile * 128) * Dm;
    const __nv_bfloat16* Al = g_Xlo + (size_t)(mtile * 128) * Dm;
    const __nv_bfloat16* Bh = g_WihHi + ((size_t)pair * G4 + ntile * 128) * Dm;
    const __nv_bfloat16* Bl = g_WihLo + ((size_t)pair * G4 + ntile * 128) * Dm;
    gemm_core(acc, Ah, Al, Dm, Bh, Bl, Dm, Dm / 64, smw);

    float* Cs = (float*)smw;
    stage_C(acc, Cs);
    __syncthreads();

    int tid = threadIdx.x;
#pragma unroll
    for (int jj = 0; jj < 16; jj++) {
        int id = jj * 256 + tid;
        int n4 = id & 31, m = id >> 5;
        float4 v = *(const float4*)&Cs[m * 132 + n4 * 4];
        float4 bz = *(const float4*)&g_bias[pair * G4 + ntile * 128 + n4 * 4];
        v.x += bz.x; v.y += bz.y; v.z += bz.z; v.w += bz.w;
        *(float4*)&g_P[((size_t)pair * Mtot + mtile * 128 + m) * G4 + ntile * 128 + n4 * 4] = v;
    }
}

// ---------------- kernel 6: one LSTM step ----------------
__global__ __launch_bounds__(256, 2) void k_step_t(int s)
{
    int ntile = blockIdx.x, mtile = blockIdx.y, pair = blockIdx.z;
    int nw = pair >> 1, dir = pair & 1, w = 3 + 2 * nw;
    if (s >= w) return;
    int half = nw + 1;
    int jstep = dir ? (w - 1 - s) : s;
    int bufr = s & 1, bufw = (s + 1) & 1;

    extern __shared__ uint32_t smw[];
    float acc[4][4][4];
#pragma unroll
    for (int i = 0; i < 4; i++)
#pragma unroll
        for (int j = 0; j < 4; j++)
#pragma unroll
            for (int q = 0; q < 4; q++) acc[i][j][q] = 0.f;

    const __nv_bfloat16* Ah = g_Hhi[bufr] + ((size_t)pair * Mtot + mtile * 128) * Hh;
    const __nv_bfloat16* Al = g_Hlo[bufr] + ((size_t)pair * Mtot + mtile * 128) * Hh;
    const __nv_bfloat16* Bh = g_WhhHi + ((size_t)pair * G4 + ntile * 128) * Hh;
    const __nv_bfloat16* Bl = g_WhhLo + ((size_t)pair * G4 + ntile * 128) * Hh;
    gemm_core(acc, Ah, Al, Hh, Bh, Bl, Hh, Hh / 64, smw);

    float* Cs = (float*)smw;
    stage_C(acc, Cs);
    __syncthreads();

    int tid = threadIdx.x;
#pragma unroll
    for (int jj = 0; jj < 16; jj++) {
        int id = jj * 256 + tid;
        int hc = id & 31, m = id >> 5;
        int prow = mtile * 128 + m;
        int b = prow >> 8, l = prow & 255;
        int tpos = l - half + jstep;
        bool mask = (tpos >= 0) && (tpos < Lseq);
        int tcl = min(max(tpos, 0), Lseq - 1);
        size_t hidx = ((size_t)pair * Mtot + prow) * Hh + ntile * 32 + hc;
        if (mask) {
            float4 gv = *(const float4*)&Cs[m * 132 + hc * 4];
            float4 pv = *(const float4*)&g_P[((size_t)pair * Mtot + (b << 8) + tcl) * G4
                                             + ntile * 128 + hc * 4];
            float gi = gv.x + pv.x;
            float gf = gv.y + pv.y;
            float gg = gv.z + pv.z;
            float go = gv.w + pv.w;
            float si = 1.f / (1.f + __expf(-gi));
            float sf = 1.f / (1.f + __expf(-gf));
            float tg = tanhf(gg);
            float so = 1.f / (1.f + __expf(-go));
            float c_new = sf * g_C[hidx] + si * tg;
            float h_new = so * tanhf(c_new);
            g_C[hidx] = c_new;
            __nv_bfloat16 hi = __float2bfloat16(h_new);
            g_Hhi[bufw][hidx] = hi;
            g_Hlo[bufw][hidx] = __float2bfloat16(h_new - __bfloat162float(hi));
        } else {
            g_Hhi[bufw][hidx] = g_Hhi[bufr][hidx];
            g_Hlo[bufw][hidx] = g_Hlo[bufr][hidx];
        }
    }
}

// ---------------- kernel 7: attention + residual + head ----------------
__device__ __forceinline__ float blockReduce(float v)
{
    __shared__ float sred[8];
#pragma unroll
    for (int o = 16; o > 0; o >>= 1) v += __shfl_xor_sync(0xffffffffu, v, o);
    int wid = threadIdx.x >> 5, ln = threadIdx.x & 31;
    __syncthreads();
    if (ln == 0) sred[wid] = v;
    __syncthreads();
    float r = 0.f;
    if (wid == 0) {
        r = (ln < 8) ? sred[ln] : 0.f;
#pragma unroll
        for (int o = 4; o > 0; o >>= 1) r += __shfl_xor_sync(0xffffffffu, r, o);
    }
    return r;
}

__global__ __launch_bounds__(256) void k_final(const float* __restrict__ lw,
                                               const float* __restrict__ lb,
                                               float* __restrict__ out)
{
    int p = blockIdx.x;
    int tid = threadIdx.x;
    const float* xp = g_x + (size_t)p * Dm;
    float xv[3], mv[4][3];
    __shared__ float attn_s[4];
#pragma unroll
    for (int q = 0; q < 3; q++) xv[q] = xp[tid + q * 256];

    float logits[4];
#pragma unroll
    for (int nw = 0; nw < 4; nw++) {
        size_t fo = ((size_t)(nw * 2) * Mtot + p) * Hh;
        size_t bo = ((size_t)(nw * 2 + 1) * Mtot + p) * Hh;
#pragma unroll
        for (int q = 0; q < 3; q++) {
            int d = tid + q * 256;
            float v;
            if (d < Hh)
                v = __bfloat162float(g_Hhi[1][fo + d]) + __bfloat162float(g_Hlo[1][fo + d]);
            else
                v = __bfloat162float(g_Hhi[1][bo + d - Hh]) + __bfloat162float(g_Hlo[1][bo + d - Hh]);
            mv[nw][q] = v;
        }
        float part = xv[0] * mv[nw][0] + xv[1] * mv[nw][1] + xv[2] * mv[nw][2];
        logits[nw] = blockReduce(part);
    }
    if (tid == 0) {
        float sc = rsqrtf(768.f);
        float l0 = logits[0] * sc, l1 = logits[1] * sc, l2 = logits[2] * sc, l3 = logits[3] * sc;
        float mx = fmaxf(fmaxf(l0, l1), fmaxf(l2, l3));
        float e0 = __expf(l0 - mx), e1 = __expf(l1 - mx), e2 = __expf(l2 - mx), e3 = __expf(l3 - mx);
        float inv = 1.f / (e0 + e1 + e2 + e3);
        attn_s[0] = e0 * inv; attn_s[1] = e1 * inv; attn_s[2] = e2 * inv; attn_s[3] = e3 * inv;
    }
    __syncthreads();
    float a0 = attn_s[0], a1 = attn_s[1], a2 = attn_s[2], a3 = attn_s[3];
    float ov[3];
#pragma unroll
    for (int q = 0; q < 3; q++)
        ov[q] = xv[q] + a0 * mv[0][q] + a1 * mv[1][q] + a2 * mv[2][q] + a3 * mv[3][q];

    for (int k = 0; k < 9; k++) {
        float part = 0.f;
#pragma unroll
        for (int q = 0; q < 3; q++) part += ov[q] * lw[(size_t)k * Dm + tid + q * 256];
        float tot = blockReduce(part);
        if (tid == 0) out[p * 9 + k] = tot + lb[k];
    }
}

// ---------------- launch ----------------
extern "C" void kernel_launch(void* const* d_in, const int* in_sizes, int n_in,
                              void* d_out, int out_size)
{
    const float* seq   = (const float*)d_in[0];
    const int*   valid = (const int*)d_in[1];
    const float* wif   = (const float*)d_in[2];
    const float* whf   = (const float*)d_in[3];
    const float* bif   = (const float*)d_in[4];
    const float* bhf   = (const float*)d_in[5];
    const float* wib   = (const float*)d_in[6];
    const float* whb   = (const float*)d_in[7];
    const float* bib   = (const float*)d_in[8];
    const float* bhb   = (const float*)d_in[9];
    const float* lw    = (const float*)d_in[10];
    const float* lb    = (const float*)d_in[11];
    float* out = (float*)d_out;

    static int attr_done = 0;
    if (!attr_done) {
        cudaFuncSetAttribute(k_proj_t, cudaFuncAttributeMaxDynamicSharedMemorySize, SMEM_BYTES);
        cudaFuncSetAttribute(k_step_t, cudaFuncAttributeMaxDynamicSharedMemorySize, SMEM_BYTES);
        attr_done = 1;
    }

    k_scatter<<<Bsz, 256>>>(seq, valid);
    k_convX<<<512, 256>>>();
    k_zero<<<512, 256>>>();
    k_convW<<<1024, 256>>>(whf, whb, wif, wib, bif, bhf, bib, bhb);
    k_proj_t<<<dim3(NT, 8, NPAIR), 256, SMEM_BYTES>>>();
    for (int s = 0; s < 9; s++)
        k_step_t<<<dim3(NT, 8, NPAIR), 256, SMEM_BYTES>>>(s);
    k_final<<<Mtot, 256>>>(lw, lb, out);
}